// round 13
// baseline (speedup 1.0000x reference)
#include <cuda_runtime.h>
#include <cuda_bf16.h>
#include <cstdint>

// out = conv3x3(f(img), W)/27, f(x)=P01+P11*x+P21*x^2, zero pad.
// ldmatrix + mma.sync.m16n8k16 bf16; fp32 accuracy via 3-term bf16 split.
// Round 13: round-12 structure (all 4 A rows resident, 4-slot cp.async B
// ring, pure ldsm+MMA phases) with the prologue fill bug fixed: full 32
// channels staged per z row (2 batches of 2 rows).

#define HW     128
#define CIN    64
#define COUT   64
#define ATILE  16640                // [130 px][64 c] bf16 (128 B rows)
#define BSLOT  16384                // one tap: 2 parts x 8KB swizzled image
#define BOFF   0
#define AOFF   (4 * BSLOT)          // 65536
#define DSMEM  (AOFF + 8 * ATILE)   // 198656

__device__ __align__(16) char g_wimg[9 * BSLOT];   // [tap][part][swizzled 8KB]

__device__ __forceinline__ uint32_t smem_u32(const void* p) {
    uint32_t a;
    asm("{ .reg .u64 t; cvta.to.shared.u64 t, %1; cvt.u32.u64 %0, t; }" : "=r"(a) : "l"(p));
    return a;
}
__device__ __forceinline__ void ldsm4(uint32_t* r, uint32_t a) {
    asm volatile("ldmatrix.sync.aligned.m8n8.x4.shared.b16 {%0,%1,%2,%3}, [%4];"
        : "=r"(r[0]), "=r"(r[1]), "=r"(r[2]), "=r"(r[3]) : "r"(a));
}
__device__ __forceinline__ void mma_bf16(float* d, const uint32_t* a, const uint32_t* b) {
    asm volatile("mma.sync.aligned.m16n8k16.row.col.f32.bf16.bf16.f32 "
        "{%0,%1,%2,%3}, {%4,%5,%6,%7}, {%8,%9}, {%0,%1,%2,%3};"
        : "+f"(d[0]), "+f"(d[1]), "+f"(d[2]), "+f"(d[3])
        : "r"(a[0]), "r"(a[1]), "r"(a[2]), "r"(a[3]), "r"(b[0]), "r"(b[1]));
}
__device__ __forceinline__ void cp16(uint32_t saddr, const void* g) {
    asm volatile("cp.async.cg.shared.global [%0], [%1], 16;"
        :: "r"(saddr), "l"(__cvta_generic_to_global(g)) : "memory");
}
#define CP_COMMIT() asm volatile("cp.async.commit_group;" ::: "memory")
#define CP_WAIT2()  asm volatile("cp.async.wait_group 2;" ::: "memory")

__global__ void wprep_kernel(const float* __restrict__ wgt) {
    int idx = blockIdx.x * 256 + threadIdx.x;
    if (idx >= 9 * 64 * 64) return;
    int t = idx >> 12, k = (idx >> 6) & 63, c = idx & 63;
    float w = wgt[(k * 64 + c) * 9 + t];
    __nv_bfloat16 wh = __float2bfloat16(w);
    __nv_bfloat16 wl = __float2bfloat16(w - __bfloat162float(wh));
    int off = k * 128 + (((c >> 3) ^ (k & 7)) << 4) + (((c >> 1) & 3) << 2) + ((c & 1) << 1);
    *reinterpret_cast<__nv_bfloat16*>(g_wimg + t * BSLOT + off)        = wh;
    *reinterpret_cast<__nv_bfloat16*>(g_wimg + t * BSLOT + 8192 + off) = wl;
}

__global__ __launch_bounds__(256, 1)
void conv_hmma_kernel(const float* __restrict__ img, float* __restrict__ out)
{
    extern __shared__ __align__(1024) char dsm[];
    const uint32_t sb = smem_u32(dsm);

    const int tid  = threadIdx.x, wid = tid >> 5, lane = tid & 31;
    const int n    = blockIdx.x >> 6;
    const int yb   = (blockIdx.x & 63) * 2;
    const int p0   = wid * 16;
    const int px   = tid & 127, chalf = tid >> 7;

    const float P01 = -0.000287f, P11 = 0.266f, P21 = -0.1097f;

    // ---- prologue ----
    // async-copy taps 0..2 into ring slots 0..2 (one commit each)
    #pragma unroll
    for (int g = 0; g < 3; g++) {
        #pragma unroll
        for (int j = 0; j < 4; j++) {
            int o = (tid + j * 256) * 16;
            cp16(sb + BOFF + g * BSLOT + o, g_wimg + g * BSLOT + o);
        }
        CP_COMMIT();
    }
    // zero halo px-rows (0,129) of all 8 A tiles
    for (int j = tid; j < 8 * 2 * 32; j += 256) {
        int tile = j >> 6, rem = j & 63;
        int rw = (rem >> 5) ? 129 : 0, col = rem & 31;
        *reinterpret_cast<uint32_t*>(dsm + AOFF + tile * ATILE + rw * 128 + col * 4) = 0u;
    }
    // zero whole tiles of OOB z slots
    #pragma unroll
    for (int slot = 0; slot < 4; slot++) {
        int z = yb - 1 + slot;
        if ((unsigned)z < HW) continue;
        char* a0 = dsm + AOFF + slot * 2 * ATILE;
        for (int i = tid; i < 2 * ATILE / 4; i += 256)
            reinterpret_cast<uint32_t*>(a0)[i] = 0u;
    }
    // A fill: 2 batches x 2 z-rows; each thread stages 32 channels per row
    const int rs = px + 1;
    #pragma unroll
    for (int sp = 0; sp < 2; sp++) {
        float v[2][32];
        #pragma unroll
        for (int q = 0; q < 2; q++) {
            int z = yb - 1 + sp * 2 + q;
            if ((unsigned)z >= HW) continue;
            const float* ip = img + ((size_t)(n * CIN + chalf * 32) * HW + z) * HW + px;
            #pragma unroll
            for (int i = 0; i < 32; i++) v[q][i] = ip[(size_t)i * HW * HW];
        }
        #pragma unroll
        for (int q = 0; q < 2; q++) {
            int slot = sp * 2 + q;
            int z = yb - 1 + slot;
            if ((unsigned)z >= HW) continue;
            char* a0 = dsm + AOFF + slot * 2 * ATILE;
            #pragma unroll
            for (int i = 0; i < 16; i++) {
                float x0 = v[q][2 * i], x1 = v[q][2 * i + 1];
                float v0 = fmaf(fmaf(P21, x0, P11), x0, P01);
                float v1 = fmaf(fmaf(P21, x1, P11), x1, P01);
                __nv_bfloat16 h0 = __float2bfloat16(v0), h1 = __float2bfloat16(v1);
                __nv_bfloat16 l0 = __float2bfloat16(v0 - __bfloat162float(h0));
                __nv_bfloat16 l1 = __float2bfloat16(v1 - __bfloat162float(h1));
                uint32_t hp = ((uint32_t)__bfloat16_as_ushort(h1) << 16) | __bfloat16_as_ushort(h0);
                uint32_t lp = ((uint32_t)__bfloat16_as_ushort(l1) << 16) | __bfloat16_as_ushort(l0);
                int c2 = chalf * 32 + 2 * i;
                int off = rs * 128 + ((((c2 >> 3) ^ (rs & 7))) << 4) + (c2 & 7) * 2;
                *reinterpret_cast<uint32_t*>(a0 + off)         = hp;
                *reinterpret_cast<uint32_t*>(a0 + ATILE + off) = lp;
            }
        }
    }
    CP_WAIT2();
    __syncthreads();

    float acc[2][8][4];
    #pragma unroll
    for (int yi = 0; yi < 2; yi++)
        #pragma unroll
        for (int nt = 0; nt < 8; nt++)
            #pragma unroll
            for (int e = 0; e < 4; e++) acc[yi][nt][e] = 0.f;

    // ---- 9 pure-MMA phases ----
    int p = 0;
    for (int r = 0; r < 3; r++) {
        #pragma unroll
        for (int s = 0; s < 3; s++, p++) {
            // issue next tap's copy into slot (p+3)&3 (slot was last read in phase p-1)
            if (r < 2) {
                const char* src = g_wimg + (p + 3) * BSLOT;
                uint32_t dst = sb + BOFF + ((p + 3) & 3) * BSLOT;
                #pragma unroll
                for (int j = 0; j < 4; j++) {
                    int o = (tid + j * 256) * 16;
                    cp16(dst + o, src + o);
                }
            }
            CP_COMMIT();

            // A fragments
            uint32_t af[2][2][4][4];
            const int rowA = p0 + s + (lane & 7) + ((lane >> 3) & 1) * 8;
            const int chA  = lane >> 4;
            #pragma unroll
            for (int yi = 0; yi < 2; yi++) {
                uint32_t ay = sb + AOFF + (r + yi) * 2 * ATILE + rowA * 128;
                #pragma unroll
                for (int part = 0; part < 2; part++)
                    #pragma unroll
                    for (int kc = 0; kc < 4; kc++) {
                        int ch = 2 * kc + chA;
                        ldsm4(af[yi][part][kc], ay + part * ATILE + ((ch ^ (rowA & 7)) << 4));
                    }
            }
            // B fragments double-buffered over nt2
            const uint32_t btile = sb + BOFF + (p & 3) * BSLOT;
            const int chB = (lane >> 3) & 1;
            uint32_t bf[2][2][4][4];
            auto loadB = [&](uint32_t (*dst)[4][4], int nt2) {
                const int nrow = (nt2 * 2 + (lane >> 4)) * 8 + (lane & 7);
                #pragma unroll
                for (int part = 0; part < 2; part++)
                    #pragma unroll
                    for (int kc = 0; kc < 4; kc++) {
                        int ch = 2 * kc + chB;
                        ldsm4(dst[part][kc],
                              btile + part * 8192 + nrow * 128 + ((ch ^ (nrow & 7)) << 4));
                    }
            };
            loadB(bf[0], 0);
            #pragma unroll
            for (int nt2 = 0; nt2 < 4; nt2++) {
                if (nt2 < 3) loadB(bf[(nt2 + 1) & 1], nt2 + 1);
                uint32_t (*b)[4][4] = bf[nt2 & 1];
                #pragma unroll
                for (int kc = 0; kc < 4; kc++)
                    #pragma unroll
                    for (int yi = 0; yi < 2; yi++) {
                        mma_bf16(acc[yi][nt2 * 2],     af[yi][0][kc], b[0][kc]);      // hh
                        mma_bf16(acc[yi][nt2 * 2 + 1], af[yi][0][kc], b[0][kc] + 2);
                        mma_bf16(acc[yi][nt2 * 2],     af[yi][1][kc], b[0][kc]);      // lh
                        mma_bf16(acc[yi][nt2 * 2 + 1], af[yi][1][kc], b[0][kc] + 2);
                        mma_bf16(acc[yi][nt2 * 2],     af[yi][0][kc], b[1][kc]);      // hl
                        mma_bf16(acc[yi][nt2 * 2 + 1], af[yi][0][kc], b[1][kc] + 2);
                    }
            }

            CP_WAIT2();
            __syncthreads();
        }
    }

    // ---- epilogue: scale by 1/27 ----
    const float sc = 1.f / 27.f;
    #pragma unroll
    for (int yi = 0; yi < 2; yi++) {
        const int y = yb + yi;
        #pragma unroll
        for (int nt = 0; nt < 8; nt++) {
            int kout = nt * 8 + 2 * (lane & 3);
            int pxo  = p0 + (lane >> 2);
            float* o = out + ((size_t)(n * COUT + kout) * HW + y) * HW;
            o[pxo]               = acc[yi][nt][0] * sc;
            o[HW * HW + pxo]     = acc[yi][nt][1] * sc;
            o[pxo + 8]           = acc[yi][nt][2] * sc;
            o[HW * HW + pxo + 8] = acc[yi][nt][3] * sc;
        }
    }
}

extern "C" void kernel_launch(void* const* d_in, const int* in_sizes, int n_in,
                              void* d_out, int out_size)
{
    const float* img = (const float*)d_in[0];
    const float* wgt = (const float*)d_in[1];
    float* out = (float*)d_out;

    cudaFuncSetAttribute(conv_hmma_kernel,
                         cudaFuncAttributeMaxDynamicSharedMemorySize, DSMEM);

    int N = in_sizes[0] / (CIN * HW * HW);   // 16
    wprep_kernel<<<144, 256>>>(wgt);
    conv_hmma_kernel<<<N * 64, 256, DSMEM>>>(img, out);
}

// round 14
// speedup vs baseline: 1.2819x; 1.2819x over previous
#include <cuda_runtime.h>
#include <cuda_fp16.h>
#include <cstdint>

// out = conv3x3(f(img), W)/27, f(x)=P01+P11*x+P21*x^2, zero pad.
// ldmatrix + mma.sync.m16n8k16 fp16 (fp32 acc). Accuracy: x split into
// xh+xl (fp16 2-term), w single fp16 -> residual ~2^-11, global ~1e-4.
// Round 14: ALL smem resident (B 72KB + A 133KB), mainloop barrier-free.

#define HW     128
#define CIN    64
#define COUT   64
#define ATILE  16640                // [130 px][64 c] fp16 (128 B rows)
#define BSLOT  8192                 // one tap: [64 n][64 k] fp16 swizzled image
#define BOFF   0
#define AOFF   (9 * BSLOT)          // 73728
#define DSMEM  (AOFF + 8 * ATILE)   // 206848

__device__ __align__(16) char g_wimg[9 * BSLOT];

__device__ __forceinline__ uint32_t smem_u32(const void* p) {
    uint32_t a;
    asm("{ .reg .u64 t; cvta.to.shared.u64 t, %1; cvt.u32.u64 %0, t; }" : "=r"(a) : "l"(p));
    return a;
}
__device__ __forceinline__ void ldsm4(uint32_t* r, uint32_t a) {
    asm volatile("ldmatrix.sync.aligned.m8n8.x4.shared.b16 {%0,%1,%2,%3}, [%4];"
        : "=r"(r[0]), "=r"(r[1]), "=r"(r[2]), "=r"(r[3]) : "r"(a));
}
__device__ __forceinline__ void mma_f16(float* d, const uint32_t* a, const uint32_t* b) {
    asm volatile("mma.sync.aligned.m16n8k16.row.col.f32.f16.f16.f32 "
        "{%0,%1,%2,%3}, {%4,%5,%6,%7}, {%8,%9}, {%0,%1,%2,%3};"
        : "+f"(d[0]), "+f"(d[1]), "+f"(d[2]), "+f"(d[3])
        : "r"(a[0]), "r"(a[1]), "r"(a[2]), "r"(a[3]), "r"(b[0]), "r"(b[1]));
}
__device__ __forceinline__ void cp16(uint32_t saddr, const void* g) {
    asm volatile("cp.async.cg.shared.global [%0], [%1], 16;"
        :: "r"(saddr), "l"(__cvta_generic_to_global(g)) : "memory");
}
#define CP_COMMIT() asm volatile("cp.async.commit_group;" ::: "memory")
#define CP_WAIT0()  asm volatile("cp.async.wait_group 0;" ::: "memory")

__global__ void wprep_kernel(const float* __restrict__ wgt) {
    int idx = blockIdx.x * 256 + threadIdx.x;
    if (idx >= 9 * 64 * 64) return;
    int t = idx >> 12, k = (idx >> 6) & 63, c = idx & 63;
    float w = wgt[(k * 64 + c) * 9 + t];
    __half wh = __float2half(w);
    int off = k * 128 + (((c >> 3) ^ (k & 7)) << 4) + (((c >> 1) & 3) << 2) + ((c & 1) << 1);
    *reinterpret_cast<__half*>(g_wimg + t * BSLOT + off) = wh;
}

__global__ __launch_bounds__(256, 1)
void conv_hmma_kernel(const float* __restrict__ img, float* __restrict__ out)
{
    extern __shared__ __align__(1024) char dsm[];
    const uint32_t sb = smem_u32(dsm);

    const int tid  = threadIdx.x, wid = tid >> 5, lane = tid & 31;
    const int n    = blockIdx.x >> 6;
    const int yb   = (blockIdx.x & 63) * 2;
    const int p0   = wid * 16;
    const int px   = tid & 127, chalf = tid >> 7;

    const float P01 = -0.000287f, P11 = 0.266f, P21 = -0.1097f;

    // ---- prologue ----
    // all 9 B tap images: 72KB async copy (18 x 16B per thread)
    #pragma unroll
    for (int j = 0; j < 18; j++) {
        int o = (tid + j * 256) * 16;
        cp16(sb + BOFF + o, g_wimg + o);
    }
    CP_COMMIT();
    // zero halo px-rows (0,129) of all 8 A tiles
    for (int j = tid; j < 8 * 2 * 32; j += 256) {
        int tile = j >> 6, rem = j & 63;
        int rw = (rem >> 5) ? 129 : 0, col = rem & 31;
        *reinterpret_cast<uint32_t*>(dsm + AOFF + tile * ATILE + rw * 128 + col * 4) = 0u;
    }
    // zero whole tiles of OOB z slots
    #pragma unroll
    for (int slot = 0; slot < 4; slot++) {
        int z = yb - 1 + slot;
        if ((unsigned)z < HW) continue;
        char* a0 = dsm + AOFF + slot * 2 * ATILE;
        for (int i = tid; i < 2 * ATILE / 4; i += 256)
            reinterpret_cast<uint32_t*>(a0)[i] = 0u;
    }
    // A fill: 2 batches x 2 z-rows; each thread stages 32 channels per row
    const int rs = px + 1;
    #pragma unroll
    for (int sp = 0; sp < 2; sp++) {
        float v[2][32];
        #pragma unroll
        for (int q = 0; q < 2; q++) {
            int z = yb - 1 + sp * 2 + q;
            if ((unsigned)z >= HW) continue;
            const float* ip = img + ((size_t)(n * CIN + chalf * 32) * HW + z) * HW + px;
            #pragma unroll
            for (int i = 0; i < 32; i++) v[q][i] = ip[(size_t)i * HW * HW];
        }
        #pragma unroll
        for (int q = 0; q < 2; q++) {
            int slot = sp * 2 + q;
            int z = yb - 1 + slot;
            if ((unsigned)z >= HW) continue;
            char* a0 = dsm + AOFF + slot * 2 * ATILE;
            #pragma unroll
            for (int i = 0; i < 16; i++) {
                float x0 = v[q][2 * i], x1 = v[q][2 * i + 1];
                float v0 = fmaf(fmaf(P21, x0, P11), x0, P01);
                float v1 = fmaf(fmaf(P21, x1, P11), x1, P01);
                __half h0 = __float2half(v0), h1 = __float2half(v1);
                __half l0 = __float2half(v0 - __half2float(h0));
                __half l1 = __float2half(v1 - __half2float(h1));
                uint32_t hp = ((uint32_t)__half_as_ushort(h1) << 16) | __half_as_ushort(h0);
                uint32_t lp = ((uint32_t)__half_as_ushort(l1) << 16) | __half_as_ushort(l0);
                int c2 = chalf * 32 + 2 * i;
                int off = rs * 128 + ((((c2 >> 3) ^ (rs & 7))) << 4) + (c2 & 7) * 2;
                *reinterpret_cast<uint32_t*>(a0 + off)         = hp;   // xh
                *reinterpret_cast<uint32_t*>(a0 + ATILE + off) = lp;   // xl
            }
        }
    }
    CP_WAIT0();
    __syncthreads();
    // everything is read-only from here: NO more barriers until the end.

    float acc[2][8][4];
    #pragma unroll
    for (int yi = 0; yi < 2; yi++)
        #pragma unroll
        for (int nt = 0; nt < 8; nt++)
            #pragma unroll
            for (int e = 0; e < 4; e++) acc[yi][nt][e] = 0.f;

    for (int r = 0; r < 3; r++) {
        #pragma unroll
        for (int s = 0; s < 3; s++) {
            // A fragments: [yi][part][kc]
            uint32_t af[2][2][4][4];
            const int rowA = p0 + s + (lane & 7) + ((lane >> 3) & 1) * 8;
            const int chA  = lane >> 4;
            #pragma unroll
            for (int yi = 0; yi < 2; yi++) {
                uint32_t ay = sb + AOFF + (r + yi) * 2 * ATILE + rowA * 128;
                #pragma unroll
                for (int part = 0; part < 2; part++)
                    #pragma unroll
                    for (int kc = 0; kc < 4; kc++) {
                        int ch = 2 * kc + chA;
                        ldsm4(af[yi][part][kc], ay + part * ATILE + ((ch ^ (rowA & 7)) << 4));
                    }
            }
            // B fragments double-buffered over nt2 (single part: wh)
            const uint32_t btile = sb + BOFF + (r * 3 + s) * BSLOT;
            const int chB = (lane >> 3) & 1;
            uint32_t bf[2][4][4];
            auto loadB = [&](uint32_t (*dst)[4], int nt2) {
                const int nrow = (nt2 * 2 + (lane >> 4)) * 8 + (lane & 7);
                #pragma unroll
                for (int kc = 0; kc < 4; kc++) {
                    int ch = 2 * kc + chB;
                    ldsm4(dst[kc], btile + nrow * 128 + ((ch ^ (nrow & 7)) << 4));
                }
            };
            loadB(bf[0], 0);
            #pragma unroll
            for (int nt2 = 0; nt2 < 4; nt2++) {
                if (nt2 < 3) loadB(bf[(nt2 + 1) & 1], nt2 + 1);
                uint32_t (*b)[4] = bf[nt2 & 1];
                #pragma unroll
                for (int kc = 0; kc < 4; kc++)
                    #pragma unroll
                    for (int part = 0; part < 2; part++)       // xh*wh, xl*wh
                        #pragma unroll
                        for (int yi = 0; yi < 2; yi++) {
                            mma_f16(acc[yi][nt2 * 2],     af[yi][part][kc], b[kc]);
                            mma_f16(acc[yi][nt2 * 2 + 1], af[yi][part][kc], b[kc] + 2);
                        }
            }
        }
    }

    // ---- epilogue: scale by 1/27 ----
    const float sc = 1.f / 27.f;
    #pragma unroll
    for (int yi = 0; yi < 2; yi++) {
        const int y = yb + yi;
        #pragma unroll
        for (int nt = 0; nt < 8; nt++) {
            int kout = nt * 8 + 2 * (lane & 3);
            int pxo  = p0 + (lane >> 2);
            float* o = out + ((size_t)(n * COUT + kout) * HW + y) * HW;
            o[pxo]               = acc[yi][nt][0] * sc;
            o[HW * HW + pxo]     = acc[yi][nt][1] * sc;
            o[pxo + 8]           = acc[yi][nt][2] * sc;
            o[HW * HW + pxo + 8] = acc[yi][nt][3] * sc;
        }
    }
}

extern "C" void kernel_launch(void* const* d_in, const int* in_sizes, int n_in,
                              void* d_out, int out_size)
{
    const float* img = (const float*)d_in[0];
    const float* wgt = (const float*)d_in[1];
    float* out = (float*)d_out;

    cudaFuncSetAttribute(conv_hmma_kernel,
                         cudaFuncAttributeMaxDynamicSharedMemorySize, DSMEM);

    int N = in_sizes[0] / (CIN * HW * HW);   // 16
    wprep_kernel<<<144, 256>>>(wgt);
    conv_hmma_kernel<<<N * 64, 256, DSMEM>>>(img, out);
}

// round 15
// speedup vs baseline: 1.3045x; 1.0176x over previous
#include <cuda_runtime.h>
#include <cuda_fp16.h>
#include <cstdint>

// out = conv3x3(f(img), W)/27, f(x)=P01+P11*x+P21*x^2, zero pad.
// ldmatrix + mma.sync.m16n8k16 fp16 (fp32 acc). Accuracy: w split wh+wl
// (2-term), x single fp16 -> residual ~2^-11 on x only, global ~2e-4.
// Round 15: flipped split => A tiles halve; 3 output rows per block
// (5 z-rows + 18 B images all smem-resident, 230.7KB); barrier-free
// mainloop; per-block fixed costs amortized over 3 rows.

#define HW     128
#define CIN    64
#define COUT   64
#define ATILE  16640                // [130 px][64 c] fp16 (128 B rows)
#define BSLOT  8192                 // one (tap,part): [64 n][64 k] fp16 image
#define BOFF   0
#define AOFF   (18 * BSLOT)         // 147456
#define DSMEM  (AOFF + 5 * ATILE)   // 230656

__device__ __align__(16) char g_wimg[18 * BSLOT];   // [tap][part] swizzled

__device__ __forceinline__ uint32_t smem_u32(const void* p) {
    uint32_t a;
    asm("{ .reg .u64 t; cvta.to.shared.u64 t, %1; cvt.u32.u64 %0, t; }" : "=r"(a) : "l"(p));
    return a;
}
__device__ __forceinline__ void ldsm4(uint32_t* r, uint32_t a) {
    asm volatile("ldmatrix.sync.aligned.m8n8.x4.shared.b16 {%0,%1,%2,%3}, [%4];"
        : "=r"(r[0]), "=r"(r[1]), "=r"(r[2]), "=r"(r[3]) : "r"(a));
}
__device__ __forceinline__ void mma_f16(float* d, const uint32_t* a, const uint32_t* b) {
    asm volatile("mma.sync.aligned.m16n8k16.row.col.f32.f16.f16.f32 "
        "{%0,%1,%2,%3}, {%4,%5,%6,%7}, {%8,%9}, {%0,%1,%2,%3};"
        : "+f"(d[0]), "+f"(d[1]), "+f"(d[2]), "+f"(d[3])
        : "r"(a[0]), "r"(a[1]), "r"(a[2]), "r"(a[3]), "r"(b[0]), "r"(b[1]));
}
__device__ __forceinline__ void cp16(uint32_t saddr, const void* g) {
    asm volatile("cp.async.cg.shared.global [%0], [%1], 16;"
        :: "r"(saddr), "l"(__cvta_generic_to_global(g)) : "memory");
}
#define CP_COMMIT() asm volatile("cp.async.commit_group;" ::: "memory")
#define CP_WAIT0()  asm volatile("cp.async.wait_group 0;" ::: "memory")

__global__ void wprep_kernel(const float* __restrict__ wgt) {
    int idx = blockIdx.x * 256 + threadIdx.x;
    if (idx >= 9 * 64 * 64) return;
    int t = idx >> 12, k = (idx >> 6) & 63, c = idx & 63;
    float w = wgt[(k * 64 + c) * 9 + t];
    __half wh = __float2half(w);
    __half wl = __float2half(w - __half2float(wh));
    int off = k * 128 + (((c >> 3) ^ (k & 7)) << 4) + (((c >> 1) & 3) << 2) + ((c & 1) << 1);
    *reinterpret_cast<__half*>(g_wimg + (t * 2 + 0) * BSLOT + off) = wh;
    *reinterpret_cast<__half*>(g_wimg + (t * 2 + 1) * BSLOT + off) = wl;
}

__global__ __launch_bounds__(256, 1)
void conv_hmma_kernel(const float* __restrict__ img, float* __restrict__ out)
{
    extern __shared__ __align__(1024) char dsm[];
    const uint32_t sb = smem_u32(dsm);

    const int tid  = threadIdx.x, wid = tid >> 5, lane = tid & 31;
    const int n    = blockIdx.x / 43;
    const int yb   = (blockIdx.x % 43) * 3;       // 3 output rows: yb..yb+2
    const int p0   = wid * 16;
    const int px   = tid & 127, chalf = tid >> 7;

    const float P01 = -0.000287f, P11 = 0.266f, P21 = -0.1097f;

    // ---- prologue ----
    // all 18 B images: 144KB async copy (36 x 16B per thread)
    #pragma unroll
    for (int j = 0; j < 36; j++) {
        int o = (tid + j * 256) * 16;
        cp16(sb + BOFF + o, g_wimg + o);
    }
    CP_COMMIT();
    // zero halo px-rows (0,129) of all 5 A tiles
    for (int j = tid; j < 5 * 2 * 32; j += 256) {
        int tile = j >> 6, rem = j & 63;
        int rw = (rem >> 5) ? 129 : 0, col = rem & 31;
        *reinterpret_cast<uint32_t*>(dsm + AOFF + tile * ATILE + rw * 128 + col * 4) = 0u;
    }
    // zero whole tiles of OOB z slots
    #pragma unroll
    for (int slot = 0; slot < 5; slot++) {
        int z = yb - 1 + slot;
        if ((unsigned)z < HW) continue;
        char* a0 = dsm + AOFF + slot * ATILE;
        for (int i = tid; i < ATILE / 4; i += 256)
            reinterpret_cast<uint32_t*>(a0)[i] = 0u;
    }
    // A fill: batches of 2 z-rows; each thread stages 32 channels per row
    const int rs = px + 1;
    #pragma unroll
    for (int sp = 0; sp < 3; sp++) {
        const int nslot = (sp == 2) ? 1 : 2;
        float v[2][32];
        #pragma unroll
        for (int q = 0; q < 2; q++) {
            if (q >= nslot) break;
            int z = yb - 1 + sp * 2 + q;
            if ((unsigned)z >= HW) continue;
            const float* ip = img + ((size_t)(n * CIN + chalf * 32) * HW + z) * HW + px;
            #pragma unroll
            for (int i = 0; i < 32; i++) v[q][i] = ip[(size_t)i * HW * HW];
        }
        #pragma unroll
        for (int q = 0; q < 2; q++) {
            if (q >= nslot) break;
            int slot = sp * 2 + q;
            int z = yb - 1 + slot;
            if ((unsigned)z >= HW) continue;
            char* a0 = dsm + AOFF + slot * ATILE;
            #pragma unroll
            for (int i = 0; i < 16; i++) {
                float x0 = v[q][2 * i], x1 = v[q][2 * i + 1];
                float v0 = fmaf(fmaf(P21, x0, P11), x0, P01);
                float v1 = fmaf(fmaf(P21, x1, P11), x1, P01);
                __half h0 = __float2half(v0), h1 = __float2half(v1);
                uint32_t hp = ((uint32_t)__half_as_ushort(h1) << 16) | __half_as_ushort(h0);
                int c2 = chalf * 32 + 2 * i;
                int off = rs * 128 + ((((c2 >> 3) ^ (rs & 7))) << 4) + (c2 & 7) * 2;
                *reinterpret_cast<uint32_t*>(a0 + off) = hp;
            }
        }
    }
    CP_WAIT0();
    __syncthreads();
    // everything read-only from here: no more barriers.

    float acc[3][8][4];
    #pragma unroll
    for (int yi = 0; yi < 3; yi++)
        #pragma unroll
        for (int nt = 0; nt < 8; nt++)
            #pragma unroll
            for (int e = 0; e < 4; e++) acc[yi][nt][e] = 0.f;

    for (int r = 0; r < 3; r++) {
        #pragma unroll
        for (int s = 0; s < 3; s++) {
            // A fragments: [yi][kc] (single part)
            uint32_t af[3][4][4];
            const int rowA = p0 + s + (lane & 7) + ((lane >> 3) & 1) * 8;
            const int chA  = lane >> 4;
            #pragma unroll
            for (int yi = 0; yi < 3; yi++) {
                uint32_t ay = sb + AOFF + (r + yi) * ATILE + rowA * 128;
                #pragma unroll
                for (int kc = 0; kc < 4; kc++) {
                    int ch = 2 * kc + chA;
                    ldsm4(af[yi][kc], ay + ((ch ^ (rowA & 7)) << 4));
                }
            }
            // B fragments (wh, wl) double-buffered over nt2
            const uint32_t btile = sb + BOFF + (r * 3 + s) * 2 * BSLOT;
            const int chB = (lane >> 3) & 1;
            uint32_t bf[2][2][4][4];     // [pipe][part][kc][4]
            auto loadB = [&](uint32_t (*dst)[4][4], int nt2) {
                const int nrow = (nt2 * 2 + (lane >> 4)) * 8 + (lane & 7);
                #pragma unroll
                for (int part = 0; part < 2; part++)
                    #pragma unroll
                    for (int kc = 0; kc < 4; kc++) {
                        int ch = 2 * kc + chB;
                        ldsm4(dst[part][kc],
                              btile + part * BSLOT + nrow * 128 + ((ch ^ (nrow & 7)) << 4));
                    }
            };
            loadB(bf[0], 0);
            #pragma unroll
            for (int nt2 = 0; nt2 < 4; nt2++) {
                if (nt2 < 3) loadB(bf[(nt2 + 1) & 1], nt2 + 1);
                uint32_t (*b)[4][4] = bf[nt2 & 1];
                #pragma unroll
                for (int kc = 0; kc < 4; kc++)
                    #pragma unroll
                    for (int part = 0; part < 2; part++)       // x*wh, x*wl
                        #pragma unroll
                        for (int yi = 0; yi < 3; yi++) {
                            mma_f16(acc[yi][nt2 * 2],     af[yi][kc], b[part][kc]);
                            mma_f16(acc[yi][nt2 * 2 + 1], af[yi][kc], b[part][kc] + 2);
                        }
            }
        }
    }

    // ---- epilogue: scale by 1/27, guard ragged last tile ----
    const float sc = 1.f / 27.f;
    #pragma unroll
    for (int yi = 0; yi < 3; yi++) {
        const int y = yb + yi;
        if (y >= HW) break;
        #pragma unroll
        for (int nt = 0; nt < 8; nt++) {
            int kout = nt * 8 + 2 * (lane & 3);
            int pxo  = p0 + (lane >> 2);
            float* o = out + ((size_t)(n * COUT + kout) * HW + y) * HW;
            o[pxo]               = acc[yi][nt][0] * sc;
            o[HW * HW + pxo]     = acc[yi][nt][1] * sc;
            o[pxo + 8]           = acc[yi][nt][2] * sc;
            o[HW * HW + pxo + 8] = acc[yi][nt][3] * sc;
        }
    }
}

extern "C" void kernel_launch(void* const* d_in, const int* in_sizes, int n_in,
                              void* d_out, int out_size)
{
    const float* img = (const float*)d_in[0];
    const float* wgt = (const float*)d_in[1];
    float* out = (float*)d_out;

    cudaFuncSetAttribute(conv_hmma_kernel,
                         cudaFuncAttributeMaxDynamicSharedMemorySize, DSMEM);

    int N = in_sizes[0] / (CIN * HW * HW);   // 16
    wprep_kernel<<<144, 256>>>(wgt);
    conv_hmma_kernel<<<N * 43, 256, DSMEM>>>(img, out);
}

// round 16
// speedup vs baseline: 1.4415x; 1.1050x over previous
#include <cuda_runtime.h>
#include <cuda_fp16.h>
#include <cstdint>

// out = conv3x3(f(img), W)/27, f(x)=P01+P11*x+P21*x^2, zero pad.
// ldmatrix + mma.sync.m16n8k16 fp16 (fp32 acc). Accuracy: x split xh+xl,
// w single fp16 (round-14 math, rel_err ~2e-4).
// Round 16: persistent strip blocks — grid 144 (16 img x 9 strips), one
// wave. Block slides a 1-row window down its strip: 4-slot A ring (xh+xl),
// all 9 B images resident (72KB). Per iter: stage LDGs -> 576 MMAs ->
// store row -> fill z=y+2 -> barrier. Fixed costs paid once per strip.

#define HW     128
#define CIN    64
#define COUT   64
#define ATILE  16640                // [130 px][64 c] fp16 (128 B rows)
#define BSLOT  8192                 // one tap: [64 n][64 k] fp16 image
#define BOFF   0
#define AOFF   (9 * BSLOT)          // 73728
#define DSMEM  (AOFF + 8 * ATILE)   // 206848 (4 slots x 2 parts)

__device__ __align__(16) char g_wimg[9 * BSLOT];

__device__ __forceinline__ uint32_t smem_u32(const void* p) {
    uint32_t a;
    asm("{ .reg .u64 t; cvta.to.shared.u64 t, %1; cvt.u32.u64 %0, t; }" : "=r"(a) : "l"(p));
    return a;
}
__device__ __forceinline__ void ldsm4(uint32_t* r, uint32_t a) {
    asm volatile("ldmatrix.sync.aligned.m8n8.x4.shared.b16 {%0,%1,%2,%3}, [%4];"
        : "=r"(r[0]), "=r"(r[1]), "=r"(r[2]), "=r"(r[3]) : "r"(a));
}
__device__ __forceinline__ void mma_f16(float* d, const uint32_t* a, const uint32_t* b) {
    asm volatile("mma.sync.aligned.m16n8k16.row.col.f32.f16.f16.f32 "
        "{%0,%1,%2,%3}, {%4,%5,%6,%7}, {%8,%9}, {%0,%1,%2,%3};"
        : "+f"(d[0]), "+f"(d[1]), "+f"(d[2]), "+f"(d[3])
        : "r"(a[0]), "r"(a[1]), "r"(a[2]), "r"(a[3]), "r"(b[0]), "r"(b[1]));
}
__device__ __forceinline__ void cp16(uint32_t saddr, const void* g) {
    asm volatile("cp.async.cg.shared.global [%0], [%1], 16;"
        :: "r"(saddr), "l"(__cvta_generic_to_global(g)) : "memory");
}
#define CP_COMMIT() asm volatile("cp.async.commit_group;" ::: "memory")
#define CP_WAIT0()  asm volatile("cp.async.wait_group 0;" ::: "memory")

__global__ void wprep_kernel(const float* __restrict__ wgt) {
    int idx = blockIdx.x * 256 + threadIdx.x;
    if (idx >= 9 * 64 * 64) return;
    int t = idx >> 12, k = (idx >> 6) & 63, c = idx & 63;
    float w = wgt[(k * 64 + c) * 9 + t];
    __half wh = __float2half(w);
    int off = k * 128 + (((c >> 3) ^ (k & 7)) << 4) + (((c >> 1) & 3) << 2) + ((c & 1) << 1);
    *reinterpret_cast<__half*>(g_wimg + t * BSLOT + off) = wh;
}

__global__ __launch_bounds__(256, 1)
void conv_hmma_kernel(const float* __restrict__ img, float* __restrict__ out)
{
    extern __shared__ __align__(1024) char dsm[];
    const uint32_t sb = smem_u32(dsm);

    const int tid   = threadIdx.x, wid = tid >> 5, lane = tid & 31;
    const int n     = blockIdx.x / 9;
    const int strip = blockIdx.x % 9;
    const int y0    = (strip < 2) ? strip * 15 : 30 + (strip - 2) * 14;
    const int rows  = (strip < 2) ? 15 : 14;
    const int yend  = y0 + rows - 1;
    const int p0    = wid * 16;
    const int px    = tid & 127, chalf = tid >> 7;

    const float P01 = -0.000287f, P11 = 0.266f, P21 = -0.1097f;
    const int rs = px + 1;

    // fill row z into its ring slot: poly + fp16 split, swizzled STS
    auto fillA = [&](int z) {
        char* a0 = dsm + AOFF + ((z + 1) & 3) * 2 * ATILE;
        if ((unsigned)z < HW) {
            const float* ip = img + ((size_t)(n * CIN + chalf * 32) * HW + z) * HW + px;
            float v[32];
            #pragma unroll
            for (int i = 0; i < 32; i++) v[i] = ip[(size_t)i * HW * HW];
            #pragma unroll
            for (int i = 0; i < 16; i++) {
                float x0 = v[2 * i], x1 = v[2 * i + 1];
                float v0 = fmaf(fmaf(P21, x0, P11), x0, P01);
                float v1 = fmaf(fmaf(P21, x1, P11), x1, P01);
                __half h0 = __float2half(v0), h1 = __float2half(v1);
                __half l0 = __float2half(v0 - __half2float(h0));
                __half l1 = __float2half(v1 - __half2float(h1));
                uint32_t hp = ((uint32_t)__half_as_ushort(h1) << 16) | __half_as_ushort(h0);
                uint32_t lp = ((uint32_t)__half_as_ushort(l1) << 16) | __half_as_ushort(l0);
                int c2 = chalf * 32 + 2 * i;
                int off = rs * 128 + ((((c2 >> 3) ^ (rs & 7))) << 4) + (c2 & 7) * 2;
                *reinterpret_cast<uint32_t*>(a0 + off)         = hp;
                *reinterpret_cast<uint32_t*>(a0 + ATILE + off) = lp;
            }
        } else {
            for (int i = tid; i < 2 * ATILE / 4; i += 256)
                reinterpret_cast<uint32_t*>(a0)[i] = 0u;
        }
    };

    // ---- prologue (once per strip) ----
    #pragma unroll
    for (int j = 0; j < 18; j++) {          // all 9 B images, 72KB
        int o = (tid + j * 256) * 16;
        cp16(sb + BOFF + o, g_wimg + o);
    }
    CP_COMMIT();
    for (int j = tid; j < 8 * 2 * 32; j += 256) {   // halo px rows of 8 tiles
        int tile = j >> 6, rem = j & 63;
        int rw = (rem >> 5) ? 129 : 0, col = rem & 31;
        *reinterpret_cast<uint32_t*>(dsm + AOFF + tile * ATILE + rw * 128 + col * 4) = 0u;
    }
    fillA(y0 - 1);
    fillA(y0);
    fillA(y0 + 1);
    CP_WAIT0();
    __syncthreads();

    // ---- sliding-row mainloop ----
    for (int y = y0; y <= yend; y++) {
        const bool dofill = (y < yend);
        const int  zf     = y + 2;
        const bool zok    = zf < HW;

        // stage LDGs for the next fill early (latency hidden under MMAs)
        float v[32];
        if (dofill && zok) {
            const float* ip = img + ((size_t)(n * CIN + chalf * 32) * HW + zf) * HW + px;
            #pragma unroll
            for (int i = 0; i < 32; i++) v[i] = ip[(size_t)i * HW * HW];
        }

        float acc[8][4];
        #pragma unroll
        for (int nt = 0; nt < 8; nt++)
            #pragma unroll
            for (int e = 0; e < 4; e++) acc[nt][e] = 0.f;

        #pragma unroll
        for (int r = 0; r < 3; r++) {
            const uint32_t abase = sb + AOFF + ((y + r) & 3) * 2 * ATILE;  // z=y-1+r
            #pragma unroll
            for (int s = 0; s < 3; s++) {
                uint32_t af[2][4][4];
                const int rowA = p0 + s + (lane & 7) + ((lane >> 3) & 1) * 8;
                const int chA  = lane >> 4;
                #pragma unroll
                for (int part = 0; part < 2; part++)
                    #pragma unroll
                    for (int kc = 0; kc < 4; kc++) {
                        int ch = 2 * kc + chA;
                        ldsm4(af[part][kc],
                              abase + part * ATILE + rowA * 128 + ((ch ^ (rowA & 7)) << 4));
                    }
                const uint32_t btile = sb + BOFF + (r * 3 + s) * BSLOT;
                const int chB = (lane >> 3) & 1;
                uint32_t bf[2][4][4];
                auto loadB = [&](uint32_t (*dst)[4], int nt2) {
                    const int nrow = (nt2 * 2 + (lane >> 4)) * 8 + (lane & 7);
                    #pragma unroll
                    for (int kc = 0; kc < 4; kc++) {
                        int ch = 2 * kc + chB;
                        ldsm4(dst[kc], btile + nrow * 128 + ((ch ^ (nrow & 7)) << 4));
                    }
                };
                loadB(bf[0], 0);
                #pragma unroll
                for (int nt2 = 0; nt2 < 4; nt2++) {
                    if (nt2 < 3) loadB(bf[(nt2 + 1) & 1], nt2 + 1);
                    uint32_t (*b)[4] = bf[nt2 & 1];
                    #pragma unroll
                    for (int kc = 0; kc < 4; kc++)
                        #pragma unroll
                        for (int part = 0; part < 2; part++) {
                            mma_f16(acc[nt2 * 2],     af[part][kc], b[kc]);
                            mma_f16(acc[nt2 * 2 + 1], af[part][kc], b[kc] + 2);
                        }
                }
            }
        }

        // store output row y (scale by 1/27)
        const float sc = 1.f / 27.f;
        #pragma unroll
        for (int nt = 0; nt < 8; nt++) {
            int kout = nt * 8 + 2 * (lane & 3);
            int pxo  = p0 + (lane >> 2);
            float* o = out + ((size_t)(n * COUT + kout) * HW + y) * HW;
            o[pxo]               = acc[nt][0] * sc;
            o[HW * HW + pxo]     = acc[nt][1] * sc;
            o[pxo + 8]           = acc[nt][2] * sc;
            o[HW * HW + pxo + 8] = acc[nt][3] * sc;
        }

        // publish z = y+2 into the slot freed 3 iters ago
        if (dofill) {
            char* a0 = dsm + AOFF + ((zf + 1) & 3) * 2 * ATILE;
            #pragma unroll
            for (int i = 0; i < 16; i++) {
                uint32_t hp = 0u, lp = 0u;
                if (zok) {
                    float x0 = v[2 * i], x1 = v[2 * i + 1];
                    float v0 = fmaf(fmaf(P21, x0, P11), x0, P01);
                    float v1 = fmaf(fmaf(P21, x1, P11), x1, P01);
                    __half h0 = __float2half(v0), h1 = __float2half(v1);
                    __half l0 = __float2half(v0 - __half2float(h0));
                    __half l1 = __float2half(v1 - __half2float(h1));
                    hp = ((uint32_t)__half_as_ushort(h1) << 16) | __half_as_ushort(h0);
                    lp = ((uint32_t)__half_as_ushort(l1) << 16) | __half_as_ushort(l0);
                }
                int c2 = chalf * 32 + 2 * i;
                int off = rs * 128 + ((((c2 >> 3) ^ (rs & 7))) << 4) + (c2 & 7) * 2;
                *reinterpret_cast<uint32_t*>(a0 + off)         = hp;
                *reinterpret_cast<uint32_t*>(a0 + ATILE + off) = lp;
            }
            __syncthreads();
        }
    }
}

extern "C" void kernel_launch(void* const* d_in, const int* in_sizes, int n_in,
                              void* d_out, int out_size)
{
    const float* img = (const float*)d_in[0];
    const float* wgt = (const float*)d_in[1];
    float* out = (float*)d_out;

    cudaFuncSetAttribute(conv_hmma_kernel,
                         cudaFuncAttributeMaxDynamicSharedMemorySize, DSMEM);

    int N = in_sizes[0] / (CIN * HW * HW);   // 16
    wprep_kernel<<<144, 256>>>(wgt);
    conv_hmma_kernel<<<N * 9, 256, DSMEM>>>(img, out);
}

// round 17
// speedup vs baseline: 2.0735x; 1.4384x over previous
#include <cuda_runtime.h>
#include <cuda_fp16.h>
#include <cstdint>

// out = conv3x3(f(img), W)/27, f(x)=P01+P11*x+P21*x^2, zero pad.
// ldmatrix + mma.sync.m16n8k16 fp16 (fp32 acc), both operands single fp16.
// Error model (measured): x-round 2.07e-4, w-round 2.09e-4, independent ->
// RSS ~2.9e-4 << 1e-3 threshold.
// Round 17: persistent 16-row strips (grid 128, one wave), 2-row sliding
// window over a 6-slot single-part A ring; all 9 B images resident.

#define HW     128
#define CIN    64
#define COUT   64
#define ATILE  16640                // [130 px][64 c] fp16 (128 B rows)
#define BSLOT  8192                 // one tap: [64 n][64 k] fp16 image
#define BOFF   0
#define AOFF   (9 * BSLOT)          // 73728
#define DSMEM  (AOFF + 6 * ATILE)   // 173568

__device__ __align__(16) char g_wimg[9 * BSLOT];

__device__ __forceinline__ uint32_t smem_u32(const void* p) {
    uint32_t a;
    asm("{ .reg .u64 t; cvta.to.shared.u64 t, %1; cvt.u32.u64 %0, t; }" : "=r"(a) : "l"(p));
    return a;
}
__device__ __forceinline__ void ldsm4(uint32_t* r, uint32_t a) {
    asm volatile("ldmatrix.sync.aligned.m8n8.x4.shared.b16 {%0,%1,%2,%3}, [%4];"
        : "=r"(r[0]), "=r"(r[1]), "=r"(r[2]), "=r"(r[3]) : "r"(a));
}
__device__ __forceinline__ void mma_f16(float* d, const uint32_t* a, const uint32_t* b) {
    asm volatile("mma.sync.aligned.m16n8k16.row.col.f32.f16.f16.f32 "
        "{%0,%1,%2,%3}, {%4,%5,%6,%7}, {%8,%9}, {%0,%1,%2,%3};"
        : "+f"(d[0]), "+f"(d[1]), "+f"(d[2]), "+f"(d[3])
        : "r"(a[0]), "r"(a[1]), "r"(a[2]), "r"(a[3]), "r"(b[0]), "r"(b[1]));
}
__device__ __forceinline__ void cp16(uint32_t saddr, const void* g) {
    asm volatile("cp.async.cg.shared.global [%0], [%1], 16;"
        :: "r"(saddr), "l"(__cvta_generic_to_global(g)) : "memory");
}
#define CP_COMMIT() asm volatile("cp.async.commit_group;" ::: "memory")
#define CP_WAIT0()  asm volatile("cp.async.wait_group 0;" ::: "memory")

__global__ void wprep_kernel(const float* __restrict__ wgt) {
    int idx = blockIdx.x * 256 + threadIdx.x;
    if (idx >= 9 * 64 * 64) return;
    int t = idx >> 12, k = (idx >> 6) & 63, c = idx & 63;
    float w = wgt[(k * 64 + c) * 9 + t];
    __half wh = __float2half(w);
    int off = k * 128 + (((c >> 3) ^ (k & 7)) << 4) + (((c >> 1) & 3) << 2) + ((c & 1) << 1);
    *reinterpret_cast<__half*>(g_wimg + t * BSLOT + off) = wh;
}

__global__ __launch_bounds__(256, 1)
void conv_hmma_kernel(const float* __restrict__ img, float* __restrict__ out)
{
    extern __shared__ __align__(1024) char dsm[];
    const uint32_t sb = smem_u32(dsm);

    const int tid   = threadIdx.x, wid = tid >> 5, lane = tid & 31;
    const int n     = blockIdx.x >> 3;
    const int strip = blockIdx.x & 7;
    const int y0    = strip * 16;            // 16 output rows per strip
    const int p0    = wid * 16;
    const int px    = tid & 127, chalf = tid >> 7;

    const float P01 = -0.000287f, P11 = 0.266f, P21 = -0.1097f;
    const int rs = px + 1;

    // convert staged row -> fp16, swizzled STS into ring slot of z (zok=0 -> zeros)
    auto publish = [&](const float* v, int z, bool zok) {
        char* a0 = dsm + AOFF + ((z + 6) % 6) * ATILE;
        #pragma unroll
        for (int i = 0; i < 16; i++) {
            uint32_t hp = 0u;
            if (zok) {
                float x0 = v[2 * i], x1 = v[2 * i + 1];
                float v0 = fmaf(fmaf(P21, x0, P11), x0, P01);
                float v1 = fmaf(fmaf(P21, x1, P11), x1, P01);
                hp = ((uint32_t)__half_as_ushort(__float2half(v1)) << 16)
                   | __half_as_ushort(__float2half(v0));
            }
            int c2 = chalf * 32 + 2 * i;
            int off = rs * 128 + ((((c2 >> 3) ^ (rs & 7))) << 4) + (c2 & 7) * 2;
            *reinterpret_cast<uint32_t*>(a0 + off) = hp;
        }
    };
    auto stage = [&](float* v, int z) {
        const float* ip = img + ((size_t)(n * CIN + chalf * 32) * HW + z) * HW + px;
        #pragma unroll
        for (int i = 0; i < 32; i++) v[i] = ip[(size_t)i * HW * HW];
    };

    // ---- prologue (once per strip) ----
    #pragma unroll
    for (int j = 0; j < 18; j++) {          // all 9 B images, 72KB
        int o = (tid + j * 256) * 16;
        cp16(sb + BOFF + o, g_wimg + o);
    }
    CP_COMMIT();
    for (int j = tid; j < 6 * 2 * 32; j += 256) {   // halo px rows of 6 tiles
        int tile = j >> 6, rem = j & 63;
        int rw = (rem >> 5) ? 129 : 0, col = rem & 31;
        *reinterpret_cast<uint32_t*>(dsm + AOFF + tile * ATILE + rw * 128 + col * 4) = 0u;
    }
    {
        float v[32];
        #pragma unroll
        for (int z0i = 0; z0i < 4; z0i++) {
            int z = y0 - 1 + z0i;
            bool zok = (unsigned)z < HW;
            if (zok) stage(v, z);
            publish(v, z, zok);
        }
    }
    CP_WAIT0();
    __syncthreads();

    // ---- sliding 2-row mainloop: 8 iters ----
    for (int it = 0; it < 8; it++) {
        const int  y      = y0 + 2 * it;
        const bool dofill = (it < 7);
        const int  z3 = y + 3, z4 = y + 4;
        const bool ok3 = z3 < HW, ok4 = z4 < HW;

        float v1[32];
        if (dofill && ok3) stage(v1, z3);    // LDGs hidden under MMAs

        float acc[2][8][4];
        #pragma unroll
        for (int yi = 0; yi < 2; yi++)
            #pragma unroll
            for (int nt = 0; nt < 8; nt++)
                #pragma unroll
                for (int e = 0; e < 4; e++) acc[yi][nt][e] = 0.f;

        #pragma unroll
        for (int r = 0; r < 3; r++) {
            #pragma unroll
            for (int s = 0; s < 3; s++) {
                // A fragments for both rows
                uint32_t af[2][4][4];
                const int rowA = p0 + s + (lane & 7) + ((lane >> 3) & 1) * 8;
                const int chA  = lane >> 4;
                #pragma unroll
                for (int yi = 0; yi < 2; yi++) {
                    const uint32_t abase = sb + AOFF + ((y + yi - 1 + r + 6) % 6) * ATILE;
                    #pragma unroll
                    for (int kc = 0; kc < 4; kc++) {
                        int ch = 2 * kc + chA;
                        ldsm4(af[yi][kc], abase + rowA * 128 + ((ch ^ (rowA & 7)) << 4));
                    }
                }
                // B fragments double-buffered over nt2
                const uint32_t btile = sb + BOFF + (r * 3 + s) * BSLOT;
                const int chB = (lane >> 3) & 1;
                uint32_t bf[2][4][4];
                auto loadB = [&](uint32_t (*dst)[4], int nt2) {
                    const int nrow = (nt2 * 2 + (lane >> 4)) * 8 + (lane & 7);
                    #pragma unroll
                    for (int kc = 0; kc < 4; kc++) {
                        int ch = 2 * kc + chB;
                        ldsm4(dst[kc], btile + nrow * 128 + ((ch ^ (nrow & 7)) << 4));
                    }
                };
                loadB(bf[0], 0);
                #pragma unroll
                for (int nt2 = 0; nt2 < 4; nt2++) {
                    if (nt2 < 3) loadB(bf[(nt2 + 1) & 1], nt2 + 1);
                    uint32_t (*b)[4] = bf[nt2 & 1];
                    #pragma unroll
                    for (int kc = 0; kc < 4; kc++)
                        #pragma unroll
                        for (int yi = 0; yi < 2; yi++) {
                            mma_f16(acc[yi][nt2 * 2],     af[yi][kc], b[kc]);
                            mma_f16(acc[yi][nt2 * 2 + 1], af[yi][kc], b[kc] + 2);
                        }
                }
            }
        }

        // store output rows y, y+1 (scale by 1/27)
        const float sc = 1.f / 27.f;
        #pragma unroll
        for (int yi = 0; yi < 2; yi++) {
            #pragma unroll
            for (int nt = 0; nt < 8; nt++) {
                int kout = nt * 8 + 2 * (lane & 3);
                int pxo  = p0 + (lane >> 2);
                float* o = out + ((size_t)(n * COUT + kout) * HW + (y + yi)) * HW;
                o[pxo]               = acc[yi][nt][0] * sc;
                o[HW * HW + pxo]     = acc[yi][nt][1] * sc;
                o[pxo + 8]           = acc[yi][nt][2] * sc;
                o[HW * HW + pxo + 8] = acc[yi][nt][3] * sc;
            }
        }

        // fill z=y+3 (staged) and z=y+4 (staged now; acc regs are dead)
        if (dofill) {
            float v2[32];
            if (ok4) stage(v2, z4);
            publish(v1, z3, ok3);
            publish(v2, z4, ok4);
            __syncthreads();
        }
    }
}

extern "C" void kernel_launch(void* const* d_in, const int* in_sizes, int n_in,
                              void* d_out, int out_size)
{
    const float* img = (const float*)d_in[0];
    const float* wgt = (const float*)d_in[1];
    float* out = (float*)d_out;

    cudaFuncSetAttribute(conv_hmma_kernel,
                         cudaFuncAttributeMaxDynamicSharedMemorySize, DSMEM);

    int N = in_sizes[0] / (CIN * HW * HW);   // 16
    wprep_kernel<<<144, 256>>>(wgt);
    conv_hmma_kernel<<<N * 8, 256, DSMEM>>>(img, out);
}